// round 17
// baseline (speedup 1.0000x reference)
#include <cuda_runtime.h>
#include <cuda_bf16.h>
#include <math.h>

// ---------------------------------------------------------------------------
// MomentPredictor: 16-step autoregressive rollout of a 2-layer causal
// transformer (B=512, D=512, H=8, FF=2048), exact incremental decoding with
// KV cache, bf16-split mma.sync GEMMs (R16). R17: the ENTIRE rollout runs in
// ONE persistent kernel with a software grid barrier — removes ~260 graph
// nodes' worth of launch serialization (~1.9 ms of the 2.72 ms total).
// ---------------------------------------------------------------------------

#define NB   512
#define NT   16
#define NDIN 7
#define ND   512
#define NL   2
#define NH   8
#define NHD  64
#define NFF  2048

typedef __nv_bfloat16 bf16;

// ---- scratch (device globals) ----
__device__ float g_h  [NB * ND];
__device__ float g_h1 [NB * ND];
__device__ float g_q  [NB * ND];
__device__ float g_part[4 * NB * ND];
__device__ float g_kc [NL * NB * NH * NT * NHD];
__device__ float g_vc [NL * NB * NH * NT * NHD];
__device__ float g_y  [NB * 3];

// activation bf16 hi/lo mirrors (GEMM A operands)
__device__ __align__(16) bf16 gh_hi [NB * ND],  gh_lo [NB * ND];
__device__ __align__(16) bf16 gh1_hi[NB * ND],  gh1_lo[NB * ND];
__device__ __align__(16) bf16 gat_hi[NB * ND],  gat_lo[NB * ND];
__device__ __align__(16) bf16 gff_hi[NB * NFF], gff_lo[NB * NFF];

// transposed+split weights [N, K] K-major bf16
__device__ __align__(16) bf16 wqkv_hi[NL * 3 * ND * ND], wqkv_lo[NL * 3 * ND * ND];
__device__ __align__(16) bf16 wout_hi[NL * ND * ND],     wout_lo[NL * ND * ND];
__device__ __align__(16) bf16 wff1_hi[NL * NFF * ND],    wff1_lo[NL * NFF * ND];
__device__ __align__(16) bf16 wff2_hi[NL * ND * NFF],    wff2_lo[NL * ND * NFF];

// grid barrier counter: monotonic, stays a multiple of gridDim across replays
__device__ unsigned g_arrive;

__device__ __forceinline__ void split_store(float v, bf16* hi, bf16* lo, int idx) {
    bf16 h = __float2bfloat16(v);
    hi[idx] = h;
    lo[idx] = __float2bfloat16(v - __bfloat162float(h));
}

// m16n8k16 row.col bf16 -> f32 accumulate
__device__ __forceinline__ void mma_bf16(float* d, const unsigned* a, const unsigned* b) {
    asm volatile(
        "mma.sync.aligned.m16n8k16.row.col.f32.bf16.bf16.f32 "
        "{%0,%1,%2,%3}, {%4,%5,%6,%7}, {%8,%9}, {%0,%1,%2,%3};"
        : "+f"(d[0]), "+f"(d[1]), "+f"(d[2]), "+f"(d[3])
        : "r"(a[0]), "r"(a[1]), "r"(a[2]), "r"(a[3]), "r"(b[0]), "r"(b[1]));
}

// ---------------------------------------------------------------------------
// software grid barrier. __threadfence() (gpu scope) both orders the release
// and emits CCTL.IVALL, invalidating this SM's L1D so post-barrier reads of
// data written by other CTAs are fresh (L1 is not coherent within a launch).
// ---------------------------------------------------------------------------
__device__ __forceinline__ void gsync() {
    __syncthreads();
    if (threadIdx.x == 0) {
        __threadfence();                           // release (+ L1D inval)
        unsigned nb = gridDim.x;
        unsigned pos = atomicAdd(&g_arrive, 1u);
        unsigned target = (pos / nb + 1u) * nb;
        while (*(volatile unsigned*)&g_arrive < target) __nanosleep(64);
        __threadfence();                           // acquire (+ L1D inval)
    }
    __syncthreads();
}

// ---------------------------------------------------------------------------
// weight transpose + bf16 split (phase W): src [K,N] fp32 -> dst [N,K] bf16
// ---------------------------------------------------------------------------
__device__ __forceinline__ void wsplit_phase(const float* __restrict__ src,
                                             bf16* __restrict__ dhi,
                                             bf16* __restrict__ dlo,
                                             int K, int N, float (*tile)[33]) {
    int tid = threadIdx.x;
    int tx = tid & 31, ty = tid >> 5;             // 32 x 4
    int tilesN = N >> 5, tilesK = K >> 5;
    for (int j = blockIdx.x; j < tilesN * tilesK; j += gridDim.x) {
        int nb = (j % tilesN) << 5, kb = (j / tilesN) << 5;
#pragma unroll
        for (int jj = 0; jj < 8; jj++)
            tile[ty + (jj << 2)][tx] = src[(size_t)(kb + ty + (jj << 2)) * N + nb + tx];
        __syncthreads();
#pragma unroll
        for (int jj = 0; jj < 8; jj++) {
            float v = tile[tx][ty + (jj << 2)];
            bf16 h = __float2bfloat16(v);
            size_t o = (size_t)(nb + ty + (jj << 2)) * K + kb + tx;
            dhi[o] = h;
            dlo[o] = __float2bfloat16(v - __bfloat162float(h));
        }
        __syncthreads();
    }
}

// ---------------------------------------------------------------------------
// GEMM tile worker (R16 body): 64x64 tile, 128 threads, BK=32, bf16-split.
// MODE 0: QKV  1: FF1  2: out-proj partial  3: FF2 partial
// ---------------------------------------------------------------------------
__device__ __forceinline__ void gemm_tile(
    int MODE, int bm, int bn, int z,
    const bf16* __restrict__ Whi, const bf16* __restrict__ Wlo,
    const float* __restrict__ bias, int lda, int Ksub, int l, int t,
    bf16 (&Ahs)[2][64][40], bf16 (&Als)[2][64][40],
    bf16 (&Bhs)[2][64][40], bf16 (&Bls)[2][64][40]) {
    const bf16 *Ahi_g, *Alo_g;
    if (MODE == 0)      { Ahi_g = gh_hi;  Alo_g = gh_lo;  }
    else if (MODE == 1) { Ahi_g = gh1_hi; Alo_g = gh1_lo; }
    else if (MODE == 2) { Ahi_g = gat_hi; Alo_g = gat_lo; }
    else                { Ahi_g = gff_hi; Alo_g = gff_lo; }

    int tid = threadIdx.x, lane = tid & 31, warp = tid >> 5;
    int wm = warp >> 1, wn = warp & 1;
    int koff = z * Ksub;
    int lrow = tid >> 2, lcol = (tid & 3) << 3;

    float d[2][4][4];
#pragma unroll
    for (int mi = 0; mi < 2; mi++)
#pragma unroll
        for (int nj = 0; nj < 4; nj++)
#pragma unroll
            for (int e = 0; e < 4; e++) d[mi][nj][e] = 0.f;

    const bf16* Ah_p = Ahi_g + (size_t)(bm + lrow) * lda + koff + lcol;
    const bf16* Al_p = Alo_g + (size_t)(bm + lrow) * lda + koff + lcol;
    const bf16* Bh_p = Whi   + (size_t)(bn + lrow) * lda + koff + lcol;
    const bf16* Bl_p = Wlo   + (size_t)(bn + lrow) * lda + koff + lcol;
    const size_t rstep = (size_t)32 * lda;

    *(uint4*)&Ahs[0][lrow     ][lcol] = *(const uint4*)(Ah_p);
    *(uint4*)&Ahs[0][lrow + 32][lcol] = *(const uint4*)(Ah_p + rstep);
    *(uint4*)&Als[0][lrow     ][lcol] = *(const uint4*)(Al_p);
    *(uint4*)&Als[0][lrow + 32][lcol] = *(const uint4*)(Al_p + rstep);
    *(uint4*)&Bhs[0][lrow     ][lcol] = *(const uint4*)(Bh_p);
    *(uint4*)&Bhs[0][lrow + 32][lcol] = *(const uint4*)(Bh_p + rstep);
    *(uint4*)&Bls[0][lrow     ][lcol] = *(const uint4*)(Bl_p);
    *(uint4*)&Bls[0][lrow + 32][lcol] = *(const uint4*)(Bl_p + rstep);
    __syncthreads();

    const int nCh = Ksub >> 5;
    int g = lane >> 2, c2 = (lane & 3) << 1;
    for (int c = 0; c < nCh; ++c) {
        int buf = c & 1;
        uint4 pf[8];
        if (c + 1 < nCh) {
            int ko = (c + 1) << 5;
            pf[0] = *(const uint4*)(Ah_p + ko);
            pf[1] = *(const uint4*)(Ah_p + rstep + ko);
            pf[2] = *(const uint4*)(Al_p + ko);
            pf[3] = *(const uint4*)(Al_p + rstep + ko);
            pf[4] = *(const uint4*)(Bh_p + ko);
            pf[5] = *(const uint4*)(Bh_p + rstep + ko);
            pf[6] = *(const uint4*)(Bl_p + ko);
            pf[7] = *(const uint4*)(Bl_p + rstep + ko);
        }
#pragma unroll
        for (int ks = 0; ks < 2; ks++) {
            int kb = ks << 4;
            unsigned ah[2][4], al[2][4], bh[4][2], bl[4][2];
#pragma unroll
            for (int mi = 0; mi < 2; mi++) {
                int r = wm * 32 + mi * 16 + g;
                ah[mi][0] = *(const unsigned*)&Ahs[buf][r    ][kb + c2];
                ah[mi][1] = *(const unsigned*)&Ahs[buf][r + 8][kb + c2];
                ah[mi][2] = *(const unsigned*)&Ahs[buf][r    ][kb + c2 + 8];
                ah[mi][3] = *(const unsigned*)&Ahs[buf][r + 8][kb + c2 + 8];
                al[mi][0] = *(const unsigned*)&Als[buf][r    ][kb + c2];
                al[mi][1] = *(const unsigned*)&Als[buf][r + 8][kb + c2];
                al[mi][2] = *(const unsigned*)&Als[buf][r    ][kb + c2 + 8];
                al[mi][3] = *(const unsigned*)&Als[buf][r + 8][kb + c2 + 8];
            }
#pragma unroll
            for (int nj = 0; nj < 4; nj++) {
                int n = wn * 32 + nj * 8 + g;
                bh[nj][0] = *(const unsigned*)&Bhs[buf][n][kb + c2];
                bh[nj][1] = *(const unsigned*)&Bhs[buf][n][kb + c2 + 8];
                bl[nj][0] = *(const unsigned*)&Bls[buf][n][kb + c2];
                bl[nj][1] = *(const unsigned*)&Bls[buf][n][kb + c2 + 8];
            }
#pragma unroll
            for (int mi = 0; mi < 2; mi++)
#pragma unroll
                for (int nj = 0; nj < 4; nj++) {
                    mma_bf16(d[mi][nj], ah[mi], bh[nj]);
                    mma_bf16(d[mi][nj], ah[mi], bl[nj]);
                    mma_bf16(d[mi][nj], al[mi], bh[nj]);
                }
        }
        if (c + 1 < nCh) {
            int nbuf = buf ^ 1;
            *(uint4*)&Ahs[nbuf][lrow     ][lcol] = pf[0];
            *(uint4*)&Ahs[nbuf][lrow + 32][lcol] = pf[1];
            *(uint4*)&Als[nbuf][lrow     ][lcol] = pf[2];
            *(uint4*)&Als[nbuf][lrow + 32][lcol] = pf[3];
            *(uint4*)&Bhs[nbuf][lrow     ][lcol] = pf[4];
            *(uint4*)&Bhs[nbuf][lrow + 32][lcol] = pf[5];
            *(uint4*)&Bls[nbuf][lrow     ][lcol] = pf[6];
            *(uint4*)&Bls[nbuf][lrow + 32][lcol] = pf[7];
        }
        __syncthreads();
    }

#pragma unroll
    for (int mi = 0; mi < 2; mi++) {
#pragma unroll
        for (int rr = 0; rr < 2; rr++) {
            int m = bm + wm * 32 + mi * 16 + g + rr * 8;
#pragma unroll
            for (int nj = 0; nj < 4; nj++) {
#pragma unroll
                for (int cc = 0; cc < 2; cc++) {
                    int col = bn + wn * 32 + nj * 8 + c2 + cc;
                    float v = d[mi][nj][rr * 2 + cc];
                    if (MODE == 0) {
                        v += bias[col];
                        int creg = col & 511, region = col >> 9;
                        if (region == 0) {
                            g_q[m * ND + creg] = v;
                        } else if (region == 1) {
                            g_kc[(size_t)l * (NB * NH * NT * NHD) +
                                 (size_t)((m * NH + (creg >> 6)) * NT + t) * NHD + (creg & 63)] = v;
                        } else {
                            g_vc[(size_t)l * (NB * NH * NT * NHD) +
                                 (size_t)((m * NH + (creg >> 6)) * NT + t) * NHD + (creg & 63)] = v;
                        }
                    } else if (MODE == 1) {
                        v = fmaxf(v + bias[col], 0.f);
                        split_store(v, gff_hi, gff_lo, m * NFF + col);
                    } else {
                        g_part[(size_t)z * (NB * ND) + m * ND + col] = v;
                    }
                }
            }
        }
    }
}

// ---------------------------------------------------------------------------
// split-K reduce + bias + residual + LayerNorm for one row (128 threads)
// ---------------------------------------------------------------------------
__device__ __forceinline__ void redln_row(int b, const float* __restrict__ bias,
                                          const float* __restrict__ gam,
                                          const float* __restrict__ bet,
                                          int nsplit, int outsel,
                                          float* shred, float* shred2) {
    int tid = threadIdx.x, lane = tid & 31, warp = tid >> 5;
    const float* R = outsel ? g_h1 : g_h;
    float v[4];
#pragma unroll
    for (int i = 0; i < 4; i++) {
        int c = tid + (i << 7);
        float a = R[b * ND + c] + bias[c];
        for (int z = 0; z < nsplit; z++)
            a += g_part[(size_t)z * (NB * ND) + b * ND + c];
        v[i] = a;
    }
    float s = v[0] + v[1] + v[2] + v[3];
#pragma unroll
    for (int o = 16; o; o >>= 1) s += __shfl_xor_sync(0xffffffffu, s, o);
    if (lane == 0) shred[warp] = s;
    __syncthreads();
    float mean = (shred[0] + shred[1] + shred[2] + shred[3]) * (1.0f / 512.0f);

    float q = 0.f;
#pragma unroll
    for (int i = 0; i < 4; i++) { v[i] -= mean; q += v[i] * v[i]; }
#pragma unroll
    for (int o = 16; o; o >>= 1) q += __shfl_xor_sync(0xffffffffu, q, o);
    if (lane == 0) shred2[warp] = q;
    __syncthreads();
    float inv = rsqrtf((shred2[0] + shred2[1] + shred2[2] + shred2[3]) * (1.0f / 512.0f) + 1e-5f);

    float* outp = outsel ? g_h : g_h1;
    bf16* ohi = outsel ? gh_hi : gh1_hi;
    bf16* olo = outsel ? gh_lo : gh1_lo;
#pragma unroll
    for (int i = 0; i < 4; i++) {
        int c = tid + (i << 7);
        float o = v[i] * inv * gam[c] + bet[c];
        outp[b * ND + c] = o;
        split_store(o, ohi, olo, b * ND + c);
    }
}

// ---------------------------------------------------------------------------
// attention for one (b,h), one warp
// ---------------------------------------------------------------------------
__device__ __forceinline__ void attn_warp(int j, int t, int l, int lane) {
    int b = j >> 3, h = j & 7;
    const float* qp = g_q + b * ND + h * NHD;
    float q0 = qp[lane], q1 = qp[lane + 32];
    const float* kb = g_kc + (size_t)l * (NB * NH * NT * NHD) + (size_t)(b * NH + h) * NT * NHD;
    const float* vb = g_vc + (size_t)l * (NB * NH * NT * NHD) + (size_t)(b * NH + h) * NT * NHD;

    float sc[NT];
#pragma unroll
    for (int p = 0; p < NT; p++) {
        float s = -1e30f;
        if (p <= t) {
            s = q0 * kb[p * NHD + lane] + q1 * kb[p * NHD + lane + 32];
#pragma unroll
            for (int o = 16; o; o >>= 1) s += __shfl_xor_sync(0xffffffffu, s, o);
            s *= 0.125f;
        }
        sc[p] = s;
    }
    float mx = -1e30f;
#pragma unroll
    for (int p = 0; p < NT; p++) mx = fmaxf(mx, sc[p]);
    float sum = 0.f;
#pragma unroll
    for (int p = 0; p < NT; p++) { float e = expf(sc[p] - mx); sc[p] = e; sum += e; }
    float invs = 1.0f / sum;
    float o0 = 0.f, o1 = 0.f;
#pragma unroll
    for (int p = 0; p < NT; p++) {
        if (p <= t) {
            float a = sc[p] * invs;
            o0 = fmaf(a, vb[p * NHD + lane],      o0);
            o1 = fmaf(a, vb[p * NHD + lane + 32], o1);
        }
    }
    split_store(o0, gat_hi, gat_lo, b * ND + h * NHD + lane);
    split_store(o1, gat_hi, gat_lo, b * ND + h * NHD + lane + 32);
}

// ---------------------------------------------------------------------------
// the persistent whole-rollout kernel
// ---------------------------------------------------------------------------
__global__ void __launch_bounds__(128, 2) persist_k(
    const float* __restrict__ x,    const float* __restrict__ ipw,
    const float* __restrict__ ipb,  const float* __restrict__ qkvw,
    const float* __restrict__ qkvb, const float* __restrict__ outw,
    const float* __restrict__ outb, const float* __restrict__ ln1s,
    const float* __restrict__ ln1b, const float* __restrict__ ffw1,
    const float* __restrict__ ffb1, const float* __restrict__ ffw2,
    const float* __restrict__ ffb2, const float* __restrict__ ln2s,
    const float* __restrict__ ln2b, const float* __restrict__ hw,
    const float* __restrict__ hb,   float* __restrict__ out) {
    __shared__ __align__(16) bf16 Ahs[2][64][40], Als[2][64][40];
    __shared__ __align__(16) bf16 Bhs[2][64][40], Bls[2][64][40];
    __shared__ float shred[4], shred2[4];

    int tid = threadIdx.x, lane = tid & 31, warp = tid >> 5;
    int cta = blockIdx.x, ncta = gridDim.x;

    // ---- phase W: weight transpose + bf16 split ----
    {
        float (*tile)[33] = (float(*)[33]) & Ahs[0][0][0];   // 4224 B alias
#pragma unroll 1
        for (int l = 0; l < NL; l++) {
            wsplit_phase(qkvw + (size_t)l * ND * 3 * ND,
                         wqkv_hi + (size_t)l * 3 * ND * ND,
                         wqkv_lo + (size_t)l * 3 * ND * ND, ND, 3 * ND, tile);
            wsplit_phase(outw + (size_t)l * ND * ND,
                         wout_hi + (size_t)l * ND * ND,
                         wout_lo + (size_t)l * ND * ND, ND, ND, tile);
            wsplit_phase(ffw1 + (size_t)l * ND * NFF,
                         wff1_hi + (size_t)l * NFF * ND,
                         wff1_lo + (size_t)l * NFF * ND, ND, NFF, tile);
            wsplit_phase(ffw2 + (size_t)l * NFF * ND,
                         wff2_hi + (size_t)l * ND * NFF,
                         wff2_lo + (size_t)l * ND * NFF, NFF, ND, tile);
        }
    }
    gsync();

#pragma unroll 1
    for (int t = 0; t < NT; t++) {
        // ---- embed ----
        for (int e = cta * 128 + tid; e < NB * ND; e += ncta * 128) {
            int b = e >> 9, dd = e & 511;
            const float* xr = x + (b * NT + t) * NDIN;
            float xin[NDIN];
#pragma unroll
            for (int k = 0; k < NDIN; k++) xin[k] = xr[k];
            if (t > 0) {
                xin[4] = g_y[b * 3 + 0];
                xin[5] = g_y[b * 3 + 1];
                xin[6] = g_y[b * 3 + 2];
            }
            float acc = ipb[dd];
#pragma unroll
            for (int k = 0; k < NDIN; k++) acc = fmaf(xin[k], ipw[k * ND + dd], acc);
            int   i2  = (dd >> 1) << 1;
            float dv  = expf(-(float)i2 * (9.210340371976184f / 512.0f));
            float ang = (float)t * dv;
            acc += (dd & 1) ? cosf(ang) : sinf(ang);
            g_h[e] = acc;
            split_store(acc, gh_hi, gh_lo, e);
        }
        gsync();

#pragma unroll 1
        for (int l = 0; l < NL; l++) {
            const bf16* wq_hi = wqkv_hi + (size_t)l * 3 * ND * ND;
            const bf16* wq_lo = wqkv_lo + (size_t)l * 3 * ND * ND;
            const bf16* wo_hi = wout_hi + (size_t)l * ND * ND;
            const bf16* wo_lo = wout_lo + (size_t)l * ND * ND;
            const bf16* w1_hi = wff1_hi + (size_t)l * NFF * ND;
            const bf16* w1_lo = wff1_lo + (size_t)l * NFF * ND;
            const bf16* w2_hi = wff2_hi + (size_t)l * ND * NFF;
            const bf16* w2_lo = wff2_lo + (size_t)l * ND * NFF;

            // QKV: 192 tiles
            for (int j = cta; j < 192; j += ncta)
                gemm_tile(0, (j / 24) << 6, (j % 24) << 6, 0, wq_hi, wq_lo,
                          qkvb + l * 3 * ND, ND, ND, l, t, Ahs, Als, Bhs, Bls);
            gsync();
            // attention: 4096 warp jobs
            for (int j = cta * 4 + warp; j < NB * NH; j += ncta * 4)
                attn_warp(j, t, l, lane);
            gsync();
            // out-proj: 64 tiles x 2 splits
            for (int j = cta; j < 128; j += ncta) {
                int z = j >> 6, r = j & 63;
                gemm_tile(2, (r >> 3) << 6, (r & 7) << 6, z, wo_hi, wo_lo,
                          outb + l * ND, ND, ND / 2, l, t, Ahs, Als, Bhs, Bls);
            }
            gsync();
            for (int b = cta; b < NB; b += ncta)
                redln_row(b, outb + l * ND, ln1s + l * ND, ln1b + l * ND, 2, 0, shred, shred2);
            gsync();
            // FF1: 256 tiles
            for (int j = cta; j < 256; j += ncta)
                gemm_tile(1, (j / 32) << 6, (j % 32) << 6, 0, w1_hi, w1_lo,
                          ffb1 + l * NFF, ND, ND, l, t, Ahs, Als, Bhs, Bls);
            gsync();
            // FF2: 64 tiles x 4 splits
            for (int j = cta; j < 256; j += ncta) {
                int z = j >> 6, r = j & 63;
                gemm_tile(3, (r >> 3) << 6, (r & 7) << 6, z, w2_hi, w2_lo,
                          ffb2 + l * ND, NFF, NFF / 4, l, t, Ahs, Als, Bhs, Bls);
            }
            gsync();
            for (int b = cta; b < NB; b += ncta)
                redln_row(b, ffb2 + l * ND, ln2s + l * ND, ln2b + l * ND, 4, 1, shred, shred2);
            gsync();
        }

        // ---- head: warp per batch row ----
        for (int b = cta * 4 + warp; b < NB; b += ncta * 4) {
#pragma unroll
            for (int w = 0; w < 3; w++) {
                float acc = 0.f;
#pragma unroll
                for (int i = 0; i < 16; i++) {
                    int dd = lane + (i << 5);
                    acc = fmaf(g_h[b * ND + dd], hw[dd * 3 + w], acc);
                }
#pragma unroll
                for (int o = 16; o; o >>= 1) acc += __shfl_xor_sync(0xffffffffu, acc, o);
                if (lane == 0) {
                    float v = acc + hb[w];
                    out[(b * NT + t) * 3 + w] = v;
                    g_y[b * 3 + w] = v;
                }
            }
        }
        gsync();
    }
}

// ---------------------------------------------------------------------------
extern "C" void kernel_launch(void* const* d_in, const int* in_sizes, int n_in,
                              void* d_out, int out_size) {
    const float* x    = (const float*)d_in[0];
    const float* ipw  = (const float*)d_in[1];
    const float* ipb  = (const float*)d_in[2];
    const float* qkvw = (const float*)d_in[3];
    const float* qkvb = (const float*)d_in[4];
    const float* outw = (const float*)d_in[5];
    const float* outb = (const float*)d_in[6];
    const float* ln1s = (const float*)d_in[7];
    const float* ln1b = (const float*)d_in[8];
    const float* ffw1 = (const float*)d_in[9];
    const float* ffb1 = (const float*)d_in[10];
    const float* ffw2 = (const float*)d_in[11];
    const float* ffb2 = (const float*)d_in[12];
    const float* ln2s = (const float*)d_in[13];
    const float* ln2b = (const float*)d_in[14];
    const float* hw   = (const float*)d_in[15];
    const float* hb   = (const float*)d_in[16];
    float* out = (float*)d_out;

    (void)in_sizes; (void)n_in; (void)out_size;

    int dev = 0;
    cudaGetDevice(&dev);
    int sms = 0;
    cudaDeviceGetAttribute(&sms, cudaDevAttrMultiProcessorCount, dev);
    int maxB = 0;
    cudaOccupancyMaxActiveBlocksPerMultiprocessor(&maxB, persist_k, 128, 0);
    if (maxB < 1) maxB = 1;
    if (maxB > 2) maxB = 2;
    int grid = sms * maxB;     // guaranteed co-resident -> barrier cannot hang

    persist_k<<<grid, 128>>>(x, ipw, ipb, qkvw, qkvb, outw, outb, ln1s, ln1b,
                             ffw1, ffb1, ffw2, ffb2, ln2s, ln2b, hw, hb, out);
}